// round 10
// baseline (speedup 1.0000x reference)
#include <cuda_runtime.h>
#include <math.h>

#define Bz 4
#define Cz 12
#define Hh 256
#define Ww 256
#define HW 65536
#define NMASK 96
#define HALFM 48
#define SENT16 65535u
#define SENT_F 1e12f        // == fl32(1e6f*1e6f)
#define SCAN_INF (1 << 20)
#define CFAKE 10000
#define BIGU 0x0FFFFFFFu

// ---------------- scratch ----------------------------------------------------
__device__ unsigned char g_mask[NMASK * HW];
__device__ unsigned int  g_g[NMASK * HW];        // packed col dist (lo=fg, hi=bg)
__device__ float         g_f2[NMASK * HW];       // field^2 per mask
__device__ float         g_e2[HALFM * HW];       // (softmax - onehot)^2 planes
__device__ int           g_hasfg[NMASK];
__device__ int           g_anyfalse[NMASK];
__device__ double        g_acc[2];               // [0]=hausdorff S, [1]=sum logp
__device__ int           g_is64;
__device__ unsigned int  g_done;

// ---------------- K0 ---------------------------------------------------------
__global__ void k0_init(const unsigned int* __restrict__ tgt_words) {
    int t = threadIdx.x;                          // 128 threads
    __shared__ int s_nz;
    if (t == 0) s_nz = 0;
    __syncthreads();
    if (tgt_words[2 * t + 1] != 0u) atomicOr(&s_nz, 1);
    if (t < NMASK) { g_hasfg[t] = 0; g_anyfalse[t] = 0; }
    __syncthreads();
    if (t == 0) {
        g_is64 = (s_nz == 0);
        g_acc[0] = 0.0;
        g_acc[1] = 0.0;
        g_done = 0u;
    }
}

__device__ __forceinline__ int load_target(const void* t, int idx) {
    if (g_is64) return (int)((const long long*)t)[idx];
    return ((const int*)t)[idx];
}

// ---------------- K1: softmax -> masks + e2 planes + CE partial --------------
__global__ void k1_masks(const float* __restrict__ pred, const void* __restrict__ tgt) {
    int pix = blockIdx.x * 256 + threadIdx.x;
    int b = pix >> 16;
    int hw = pix & (HW - 1);
    const float* p = pred + (size_t)b * Cz * HW + hw;

    int t = load_target(tgt, pix);

    float v[Cz];
    float mx = -1e30f;
    float xt = 0.0f;
#pragma unroll
    for (int c = 0; c < Cz; c++) {
        v[c] = p[c * HW];
        mx = fmaxf(mx, v[c]);
        if (c == t) xt = v[c];
    }
    float s = 0.0f;
#pragma unroll
    for (int c = 0; c < Cz; c++) {
        v[c] = expf(v[c] - mx);
        s += v[c];
    }
    float inv = 1.0f / s;
#pragma unroll
    for (int c = 0; c < Cz; c++) {
        float pv = v[c] * inv;
        g_mask[(size_t)(b * Cz + c) * HW + hw] = (unsigned char)(pv > 0.5f);
        g_mask[(size_t)(HALFM + b * Cz + c) * HW + hw] = (unsigned char)(c == t);
        float e = pv - ((c == t) ? 1.0f : 0.0f);
        g_e2[(size_t)(b * Cz + c) * HW + hw] = e * e;
    }

    float logp = xt - mx - logf(s);

    __shared__ float sred[256];
    sred[threadIdx.x] = logp;
    __syncthreads();
    for (int st = 128; st > 0; st >>= 1) {
        if (threadIdx.x < st) sred[threadIdx.x] += sred[threadIdx.x + st];
        __syncthreads();
    }
    if (threadIdx.x == 0) atomicAdd(&g_acc[1], (double)sred[0]);
}

// ---------------- K2: segmented column EDT (exact) ---------------------------
__global__ void __launch_bounds__(256) k2_cols() {
    __shared__ unsigned short sfwd[Hh][64];
    __shared__ unsigned short ssum[2][4][64];

    int tid = threadIdx.x;
    int col = tid & 63;
    int seg = tid >> 6;
    int m = blockIdx.x;
    int w = blockIdx.y * 64 + col;
    const unsigned char* msk = g_mask + (size_t)m * HW + w;

    int c1 = 255, c2 = 255;
    int ff1 = 255, ff2 = 255;
    int any = 0, anyf = 0;
#pragma unroll 8
    for (int i = 0; i < 64; i++) {
        int mv = msk[(seg * 64 + i) * Ww];
        any |= mv;
        anyf |= (mv ^ 1);
        c1 = mv ? min(c1 + 1, 255) : 0;
        c2 = mv ? 0 : min(c2 + 1, 255);
        if (!mv && ff1 == 255) ff1 = i;
        if (mv && ff2 == 255) ff2 = i;
        sfwd[seg * 64 + i][col] = (unsigned short)(c1 | (c2 << 8));
    }
    ssum[0][seg][col] = (unsigned short)(c1 | (c2 << 8));
    ssum[1][seg][col] = (unsigned short)(ff1 | (ff2 << 8));

    int anyb = __syncthreads_or(any);
    if (tid == 0 && anyb) atomicOr(&g_hasfg[m], 1);
    int anyfb = __syncthreads_or(anyf);
    if (tid == 0 && anyfb) atomicOr(&g_anyfalse[m], 1);

    int af1 = 0, af2 = 0;
#pragma unroll
    for (int s = 0; s < 4; s++) {
        unsigned int fp = ssum[1][s][col];
        af1 |= ((fp & 255u) != 255u);
        af2 |= (((fp >> 8) & 255u) != 255u);
    }
    int cin1 = CFAKE, cin2 = CFAKE;
    for (int s = 0; s < seg; s++) {
        unsigned int sp = ssum[0][s][col];
        int s1 = sp & 255, s2 = (sp >> 8) & 255;
        cin1 = min((s1 == 255) ? CFAKE : s1, cin1 + 64);
        cin2 = min((s2 == 255) ? CFAKE : s2, cin2 + 64);
    }
    int bin1 = CFAKE, bin2 = CFAKE;
    for (int s = 3; s > seg; s--) {
        unsigned int fp = ssum[1][s][col];
        int f1 = fp & 255, f2 = (fp >> 8) & 255;
        bin1 = min((f1 == 255) ? CFAKE : f1, bin1 + 64);
        bin2 = min((f2 == 255) ? CFAKE : f2, bin2 + 64);
    }

    unsigned int* gout = g_g + (size_t)m * HW + w;
    int b1 = bin1, b2 = bin2;
#pragma unroll 8
    for (int i = 63; i >= 0; i--) {
        unsigned int fw = sfwd[seg * 64 + i][col];
        int f1 = fw & 255, f2 = (fw >> 8) & 255;
        b1 = (f1 == 0) ? 0 : b1 + 1;
        b2 = (f2 == 0) ? 0 : b2 + 1;
        int fa1 = min(f1, cin1 + i + 1);
        int fa2 = min(f2, cin2 + i + 1);
        int g1 = min(fa1, b1);
        int g2v = min(fa2, b2);
        unsigned int o1 = af1 ? (unsigned int)g1 : SENT16;
        unsigned int o2 = af2 ? (unsigned int)g2v : SENT16;
        gout[(seg * 64 + i) * Ww] = o1 | (o2 << 16);
    }
}

// ---------------- K3: u16-packed 2-row exact window scan -> field^2 ----------
// Block: 8 warps = 4 row-pairs x 2 polarities. The polarity exchange reuses
// each pol1 warp's own sg region (dead after its window loop) as the transfer
// buffer, saving 8KB smem -> 8 blocks/SM occupancy.
__global__ void __launch_bounds__(256) k3_win() {
    __shared__ unsigned int sg[8][768];           // [warp][256 pad | 256 data | 256 pad]
    __shared__ unsigned char sub[8][256];

    int tid = threadIdx.x;
    int w = tid >> 5;
    int lane = tid & 31;
    int pair = w >> 1;
    int pol = w & 1;
    int m = blockIdx.x;

    int hfg = g_hasfg[m];
    int afl = g_anyfalse[m];
    if (!hfg || !afl) {                           // empty mask -> 0; all-true -> SENT_F
        float val = hfg ? SENT_F : 0.0f;
        float* o = g_f2 + (size_t)m * HW + (size_t)blockIdx.y * 8 * Ww;
        for (int i = tid; i < 8 * Ww; i += 256) o[i] = val;
        return;
    }

    int r0g = blockIdx.y * 8 + pair * 2;
    const unsigned int* g0 = g_g + (size_t)m * HW + (size_t)r0g * Ww;

    // pads = saturated-inf
    for (int i = lane; i < 256; i += 32) {
        sg[w][i] = 0xFFFFFFFFu;
        sg[w][512 + i] = 0xFFFFFFFFu;
    }

    const uint4* a0 = (const uint4*)g0;
    const uint4* a1 = (const uint4*)(g0 + Ww);
    uint4 w00 = a0[lane * 2], w01 = a0[lane * 2 + 1];
    uint4 w10 = a1[lane * 2], w11 = a1[lane * 2 + 1];
    unsigned int r0w[8] = {w00.x, w00.y, w00.z, w00.w, w01.x, w01.y, w01.z, w01.w};
    unsigned int r1w[8] = {w10.x, w10.y, w10.z, w10.w, w11.x, w11.y, w11.z, w11.w};

    int x[8];
    int base = lane * 8;
#pragma unroll
    for (int i = 0; i < 8; i++) {
        unsigned int ga = pol ? (r0w[i] >> 16) : (r0w[i] & 0xffffu);
        unsigned int gb = pol ? (r1w[i] >> 16) : (r1w[i] & 0xffffu);
        unsigned int q0 = (ga == 0xffffu) ? 0xffffu : ga * ga;   // u16 exact (<=65025)
        unsigned int q1 = (gb == 0xffffu) ? 0xffffu : gb * gb;
        sg[w][256 + base + i] = q0 | (q1 << 16);
        x[i] = (int)min(ga, 300u);                // cap is exact (R clamps at 255)
    }

    // chamfer bound on row0 (scalar); row1 covered by ub+1 (1-Lipschitz)
    int f[8];
    int run = SCAN_INF;
#pragma unroll
    for (int i = 0; i < 8; i++) { run = min(x[i], run + 1); f[i] = run; }
    int v = run;
#pragma unroll
    for (int s = 1; s < 32; s <<= 1) {
        int o = __shfl_up_sync(0xffffffffu, v, s);
        if (lane >= s) v = min(v, o + 8 * s);
    }
    int e = __shfl_up_sync(0xffffffffu, v, 1);
    if (lane == 0) e = SCAN_INF;
#pragma unroll
    for (int i = 0; i < 8; i++) f[i] = min(f[i], e + 1 + i);

    int bw[8];
    run = SCAN_INF;
#pragma unroll
    for (int i = 7; i >= 0; i--) { run = min(x[i], run + 1); bw[i] = run; }
    int vb = run;
#pragma unroll
    for (int s = 1; s < 32; s <<= 1) {
        int o = __shfl_down_sync(0xffffffffu, vb, s);
        if (lane + s < 32) vb = min(vb, o + 8 * s);
    }
    int eb = __shfl_down_sync(0xffffffffu, vb, 1);
    if (lane == 31) eb = SCAN_INF;
#pragma unroll
    for (int i = 0; i < 8; i++) {
        int ub = min(min(f[i], bw[i]), min(eb + 8 - i, 255));
        sub[w][base + i] = (unsigned char)min(ub + 1, 255);
    }
    __syncwarp();

    // main packed loop
    const unsigned int* gp = &sg[w][256];
    float dfa[8], dfb[8];
#pragma unroll
    for (int i = 0; i < 8; i++) {
        int j = i * 32 + lane;
        unsigned int R = sub[w][j];
        R = __reduce_max_sync(0xffffffffu, R);
        unsigned int best = gp[j];
        unsigned int dd2 = 0u, inc2 = 0x00010001u;
        int nb = ((int)R + 7) >> 3;
        int dbase = 0;
        for (int bl = 0; bl < nb; bl++) {
#pragma unroll
            for (int u = 1; u <= 8; u++) {
                int d = dbase + u;                // d <= 256; index in [0,767] safe
                dd2 += inc2; inc2 += 0x00020002u;
                unsigned int ca = gp[j + d];
                unsigned int cb = gp[j - d];
                unsigned int c = __vminu2(ca, cb);
                best = __vminu2(best, __vaddus2(c, dd2));
            }
            dbase += 8;
            unsigned int hm = max(best & 0xffffu, best >> 16);
            hm = __reduce_max_sync(0xffffffffu, hm);
            if ((unsigned int)((dbase + 1) * (dbase + 1)) >= hm) break;
        }
        unsigned int h0 = best & 0xffffu, h1 = best >> 16;
        int ov = (h0 == 0xffffu) | (h1 == 0xffffu);
        if (__ballot_sync(0xffffffffu, ov)) {
            // exact u32 fallback (rare: true EDT^2 > 65535 -> R was 255)
            unsigned int b0 = BIGU, b1 = BIGU;
            for (int d = 0; d <= 255; d++) {
                unsigned int ds = (unsigned int)(d * d);
                unsigned int pa = gp[j + d], pb = gp[j - d];
                unsigned int v0 = pa & 0xffffu; v0 = (v0 == 0xffffu) ? BIGU : v0 + ds;
                unsigned int v1 = pa >> 16;     v1 = (v1 == 0xffffu) ? BIGU : v1 + ds;
                unsigned int u0 = pb & 0xffffu; u0 = (u0 == 0xffffu) ? BIGU : u0 + ds;
                unsigned int u1 = pb >> 16;     u1 = (u1 == 0xffffu) ? BIGU : u1 + ds;
                b0 = min(b0, min(v0, u0));
                b1 = min(b1, min(v1, u1));
            }
            dfa[i] = (float)((h0 == 0xffffu) ? b0 : h0);
            dfb[i] = (float)((h1 == 0xffffu) ? b1 : h1);
        } else {
            dfa[i] = (float)h0;
            dfb[i] = (float)h1;
        }
    }

    // polarity exchange through pol1's own (now dead) sg region, then combine:
    // field^2 = a + b + 2*sqrt(a*b)
    if (pol) {
        float* fdst = (float*)&sg[w][0];          // own region: no other reader
#pragma unroll
        for (int i = 0; i < 8; i++) {
            int j = i * 32 + lane;
            fdst[j] = dfa[i];
            fdst[256 + j] = dfb[i];
        }
    }
    __syncthreads();
    if (!pol) {
        const float* fsrc = (const float*)&sg[w + 1][0];
        float* o0 = g_f2 + (size_t)m * HW + (size_t)r0g * Ww;
        float* o1 = o0 + Ww;
#pragma unroll
        for (int i = 0; i < 8; i++) {
            int j = i * 32 + lane;
            float a = dfa[i], b = fsrc[j];
            o0[j] = a + b + 2.0f * __fsqrt_rn(a * b);
            float a2 = dfb[i], b2v = fsrc[256 + j];
            o1[j] = a2 + b2v + 2.0f * __fsqrt_rn(a2 * b2v);
        }
    }
}

// ---------------- K4: streaming loss reduce + last-block finalize ------------
__global__ void k4_loss(float* __restrict__ outp) {
    int idx = blockIdx.x * 256 + threadIdx.x;     // over HALFM*HW elements
    // e2 plane pm pairs with f2 planes pm (pred mask) and HALFM+pm (target mask)
    float e2 = g_e2[idx];
    float fP2 = g_f2[idx];
    float fT2 = g_f2[(size_t)HALFM * HW + idx];
    float term = e2 * (fP2 + fT2);

    __shared__ double sred[256];
    sred[threadIdx.x] = (double)term;
    __syncthreads();
    for (int st = 128; st > 0; st >>= 1) {
        if (threadIdx.x < st) sred[threadIdx.x] += sred[threadIdx.x + st];
        __syncthreads();
    }
    if (threadIdx.x == 0) {
        atomicAdd(&g_acc[0], sred[0]);
        __threadfence();
        unsigned int prev = atomicAdd(&g_done, 1u);
        if (prev == (unsigned int)(gridDim.x - 1)) {
            __threadfence();
            volatile double* va = g_acc;
            double S = va[0];
            double CE = va[1];
            double N = (double)Bz * (double)HW;
            outp[0] = (float)(S / N / (double)Cz / (double)Bz / 3.0 - CE / N);
        }
    }
}

// ---------------- launch -----------------------------------------------------
extern "C" void kernel_launch(void* const* d_in, const int* in_sizes, int n_in,
                              void* d_out, int out_size) {
    const float* pred = (const float*)d_in[0];
    const void*  tgt  = d_in[1];
    float* out = (float*)d_out;

    k0_init<<<1, 128>>>((const unsigned int*)tgt);
    k1_masks<<<(Bz * HW) / 256, 256>>>(pred, tgt);
    k2_cols<<<dim3(NMASK, 4), 256>>>();
    k3_win<<<dim3(NMASK, Hh / 8), 256>>>();
    k4_loss<<<(HALFM * HW) / 256, 256>>>(out);
    (void)in_sizes; (void)n_in; (void)out_size;
}

// round 11
// speedup vs baseline: 1.2797x; 1.2797x over previous
#include <cuda_runtime.h>
#include <math.h>

#define Bz 4
#define Cz 12
#define Hh 256
#define Ww 256
#define HW 65536
#define NMASK 96
#define HALFM 48
#define SENT16 65535u
#define SENT_F 1e12f        // == fl32(1e6f*1e6f)
#define SCAN_INF (1 << 20)
#define CFAKE 10000
#define BIGU 0x0FFFFFFFu

// ---------------- scratch ----------------------------------------------------
__device__ unsigned char g_mask[NMASK * HW];
__device__ unsigned int  g_g[NMASK * HW];        // packed col dist (lo=fg, hi=bg)
__device__ float         g_f2[NMASK * HW];       // field^2 per mask
__device__ int           g_hasfg[NMASK];
__device__ int           g_anyfalse[NMASK];
__device__ double        g_acc[2];               // [0]=hausdorff S, [1]=sum logp
__device__ int           g_is64;
__device__ unsigned int  g_done;

// ---------------- K0 ---------------------------------------------------------
__global__ void k0_init(const unsigned int* __restrict__ tgt_words) {
    int t = threadIdx.x;                          // 128 threads
    __shared__ int s_nz;
    if (t == 0) s_nz = 0;
    __syncthreads();
    if (tgt_words[2 * t + 1] != 0u) atomicOr(&s_nz, 1);
    if (t < NMASK) { g_hasfg[t] = 0; g_anyfalse[t] = 0; }
    __syncthreads();
    if (t == 0) {
        g_is64 = (s_nz == 0);
        g_acc[0] = 0.0;
        g_acc[1] = 0.0;
        g_done = 0u;
    }
}

__device__ __forceinline__ int load_target(const void* t, int idx) {
    if (g_is64) return (int)((const long long*)t)[idx];
    return ((const int*)t)[idx];
}

// ---------------- K1: softmax -> masks, CE partial ---------------------------
__global__ void k1_masks(const float* __restrict__ pred, const void* __restrict__ tgt) {
    int pix = blockIdx.x * 256 + threadIdx.x;
    int b = pix >> 16;
    int hw = pix & (HW - 1);
    const float* p = pred + (size_t)b * Cz * HW + hw;

    int t = load_target(tgt, pix);

    float v[Cz];
    float mx = -1e30f;
    float xt = 0.0f;
#pragma unroll
    for (int c = 0; c < Cz; c++) {
        v[c] = p[c * HW];
        mx = fmaxf(mx, v[c]);
        if (c == t) xt = v[c];
    }
    float s = 0.0f;
#pragma unroll
    for (int c = 0; c < Cz; c++) {
        v[c] = expf(v[c] - mx);
        s += v[c];
    }
    float inv = 1.0f / s;
#pragma unroll
    for (int c = 0; c < Cz; c++) {
        g_mask[(size_t)(b * Cz + c) * HW + hw] = (unsigned char)(v[c] * inv > 0.5f);
        g_mask[(size_t)(HALFM + b * Cz + c) * HW + hw] = (unsigned char)(c == t);
    }

    float logp = xt - mx - logf(s);

    __shared__ float sred[256];
    sred[threadIdx.x] = logp;
    __syncthreads();
    for (int st = 128; st > 0; st >>= 1) {
        if (threadIdx.x < st) sred[threadIdx.x] += sred[threadIdx.x + st];
        __syncthreads();
    }
    if (threadIdx.x == 0) atomicAdd(&g_acc[1], (double)sred[0]);
}

// ---------------- K2: segmented column EDT (exact) ---------------------------
__global__ void __launch_bounds__(256) k2_cols() {
    __shared__ unsigned short sfwd[Hh][64];
    __shared__ unsigned short ssum[2][4][64];

    int tid = threadIdx.x;
    int col = tid & 63;
    int seg = tid >> 6;
    int m = blockIdx.x;
    int w = blockIdx.y * 64 + col;
    const unsigned char* msk = g_mask + (size_t)m * HW + w;

    int c1 = 255, c2 = 255;
    int ff1 = 255, ff2 = 255;
    int any = 0, anyf = 0;
#pragma unroll 8
    for (int i = 0; i < 64; i++) {
        int mv = msk[(seg * 64 + i) * Ww];
        any |= mv;
        anyf |= (mv ^ 1);
        c1 = mv ? min(c1 + 1, 255) : 0;
        c2 = mv ? 0 : min(c2 + 1, 255);
        if (!mv && ff1 == 255) ff1 = i;
        if (mv && ff2 == 255) ff2 = i;
        sfwd[seg * 64 + i][col] = (unsigned short)(c1 | (c2 << 8));
    }
    ssum[0][seg][col] = (unsigned short)(c1 | (c2 << 8));
    ssum[1][seg][col] = (unsigned short)(ff1 | (ff2 << 8));

    int anyb = __syncthreads_or(any);
    if (tid == 0 && anyb) atomicOr(&g_hasfg[m], 1);
    int anyfb = __syncthreads_or(anyf);
    if (tid == 0 && anyfb) atomicOr(&g_anyfalse[m], 1);

    int af1 = 0, af2 = 0;
#pragma unroll
    for (int s = 0; s < 4; s++) {
        unsigned int fp = ssum[1][s][col];
        af1 |= ((fp & 255u) != 255u);
        af2 |= (((fp >> 8) & 255u) != 255u);
    }
    int cin1 = CFAKE, cin2 = CFAKE;
    for (int s = 0; s < seg; s++) {
        unsigned int sp = ssum[0][s][col];
        int s1 = sp & 255, s2 = (sp >> 8) & 255;
        cin1 = min((s1 == 255) ? CFAKE : s1, cin1 + 64);
        cin2 = min((s2 == 255) ? CFAKE : s2, cin2 + 64);
    }
    int bin1 = CFAKE, bin2 = CFAKE;
    for (int s = 3; s > seg; s--) {
        unsigned int fp = ssum[1][s][col];
        int f1 = fp & 255, f2 = (fp >> 8) & 255;
        bin1 = min((f1 == 255) ? CFAKE : f1, bin1 + 64);
        bin2 = min((f2 == 255) ? CFAKE : f2, bin2 + 64);
    }

    unsigned int* gout = g_g + (size_t)m * HW + w;
    int b1 = bin1, b2 = bin2;
#pragma unroll 8
    for (int i = 63; i >= 0; i--) {
        unsigned int fw = sfwd[seg * 64 + i][col];
        int f1 = fw & 255, f2 = (fw >> 8) & 255;
        b1 = (f1 == 0) ? 0 : b1 + 1;
        b2 = (f2 == 0) ? 0 : b2 + 1;
        int fa1 = min(f1, cin1 + i + 1);
        int fa2 = min(f2, cin2 + i + 1);
        int g1 = min(fa1, b1);
        int g2v = min(fa2, b2);
        unsigned int o1 = af1 ? (unsigned int)g1 : SENT16;
        unsigned int o2 = af2 ? (unsigned int)g2v : SENT16;
        gout[(seg * 64 + i) * Ww] = o1 | (o2 << 16);
    }
}

// ---------------- K3: u16-packed 2-row exact window scan -> field^2 ----------
// 27KB smem (aliased polarity exchange) + launch_bounds(256,8): 8 blocks/SM.
__global__ void __launch_bounds__(256, 8) k3_win() {
    __shared__ unsigned int sg[8][768];           // [warp][256 pad | 256 data | 256 pad]
    __shared__ unsigned char sub[8][256];

    int tid = threadIdx.x;
    int w = tid >> 5;
    int lane = tid & 31;
    int pair = w >> 1;
    int pol = w & 1;
    int m = blockIdx.x;

    int hfg = g_hasfg[m];
    int afl = g_anyfalse[m];
    if (!hfg || !afl) {                           // empty mask -> 0; all-true -> SENT_F
        float val = hfg ? SENT_F : 0.0f;
        float* o = g_f2 + (size_t)m * HW + (size_t)blockIdx.y * 8 * Ww;
        for (int i = tid; i < 8 * Ww; i += 256) o[i] = val;
        return;
    }

    int r0g = blockIdx.y * 8 + pair * 2;
    const unsigned int* g0 = g_g + (size_t)m * HW + (size_t)r0g * Ww;

    // pads = saturated-inf
    for (int i = lane; i < 256; i += 32) {
        sg[w][i] = 0xFFFFFFFFu;
        sg[w][512 + i] = 0xFFFFFFFFu;
    }

    const uint4* a0 = (const uint4*)g0;
    const uint4* a1 = (const uint4*)(g0 + Ww);
    uint4 w00 = a0[lane * 2], w01 = a0[lane * 2 + 1];
    uint4 w10 = a1[lane * 2], w11 = a1[lane * 2 + 1];
    unsigned int r0w[8] = {w00.x, w00.y, w00.z, w00.w, w01.x, w01.y, w01.z, w01.w};
    unsigned int r1w[8] = {w10.x, w10.y, w10.z, w10.w, w11.x, w11.y, w11.z, w11.w};

    int x[8];
    int base = lane * 8;
#pragma unroll
    for (int i = 0; i < 8; i++) {
        unsigned int ga = pol ? (r0w[i] >> 16) : (r0w[i] & 0xffffu);
        unsigned int gb = pol ? (r1w[i] >> 16) : (r1w[i] & 0xffffu);
        unsigned int q0 = (ga == 0xffffu) ? 0xffffu : ga * ga;   // u16 exact (<=65025)
        unsigned int q1 = (gb == 0xffffu) ? 0xffffu : gb * gb;
        sg[w][256 + base + i] = q0 | (q1 << 16);
        x[i] = (int)min(ga, 300u);                // cap is exact (R clamps at 255)
    }

    // chamfer bound on row0 (scalar); row1 covered by ub+1 (1-Lipschitz)
    int f[8];
    int run = SCAN_INF;
#pragma unroll
    for (int i = 0; i < 8; i++) { run = min(x[i], run + 1); f[i] = run; }
    int v = run;
#pragma unroll
    for (int s = 1; s < 32; s <<= 1) {
        int o = __shfl_up_sync(0xffffffffu, v, s);
        if (lane >= s) v = min(v, o + 8 * s);
    }
    int e = __shfl_up_sync(0xffffffffu, v, 1);
    if (lane == 0) e = SCAN_INF;
#pragma unroll
    for (int i = 0; i < 8; i++) f[i] = min(f[i], e + 1 + i);

    int bw[8];
    run = SCAN_INF;
#pragma unroll
    for (int i = 7; i >= 0; i--) { run = min(x[i], run + 1); bw[i] = run; }
    int vb = run;
#pragma unroll
    for (int s = 1; s < 32; s <<= 1) {
        int o = __shfl_down_sync(0xffffffffu, vb, s);
        if (lane + s < 32) vb = min(vb, o + 8 * s);
    }
    int eb = __shfl_down_sync(0xffffffffu, vb, 1);
    if (lane == 31) eb = SCAN_INF;
#pragma unroll
    for (int i = 0; i < 8; i++) {
        int ub = min(min(f[i], bw[i]), min(eb + 8 - i, 255));
        sub[w][base + i] = (unsigned char)min(ub + 1, 255);
    }
    __syncwarp();

    // main packed loop
    const unsigned int* gp = &sg[w][256];
    float dfa[8], dfb[8];
#pragma unroll
    for (int i = 0; i < 8; i++) {
        int j = i * 32 + lane;
        unsigned int R = sub[w][j];
        R = __reduce_max_sync(0xffffffffu, R);
        unsigned int best = gp[j];
        unsigned int dd2 = 0u, inc2 = 0x00010001u;
        int nb = ((int)R + 7) >> 3;
        int dbase = 0;
        for (int bl = 0; bl < nb; bl++) {
#pragma unroll
            for (int u = 1; u <= 8; u++) {
                int d = dbase + u;                // d <= 256; index in [0,767] safe
                dd2 += inc2; inc2 += 0x00020002u;
                unsigned int ca = gp[j + d];
                unsigned int cb = gp[j - d];
                unsigned int c = __vminu2(ca, cb);
                best = __vminu2(best, __vaddus2(c, dd2));
            }
            dbase += 8;
            unsigned int hm = max(best & 0xffffu, best >> 16);
            hm = __reduce_max_sync(0xffffffffu, hm);
            if ((unsigned int)((dbase + 1) * (dbase + 1)) >= hm) break;
        }
        unsigned int h0 = best & 0xffffu, h1 = best >> 16;
        int ov = (h0 == 0xffffu) | (h1 == 0xffffu);
        if (__ballot_sync(0xffffffffu, ov)) {
            // exact u32 fallback (rare: true EDT^2 > 65535 -> R was 255)
            unsigned int b0 = BIGU, b1 = BIGU;
            for (int d = 0; d <= 255; d++) {
                unsigned int ds = (unsigned int)(d * d);
                unsigned int pa = gp[j + d], pb = gp[j - d];
                unsigned int v0 = pa & 0xffffu; v0 = (v0 == 0xffffu) ? BIGU : v0 + ds;
                unsigned int v1 = pa >> 16;     v1 = (v1 == 0xffffu) ? BIGU : v1 + ds;
                unsigned int u0 = pb & 0xffffu; u0 = (u0 == 0xffffu) ? BIGU : u0 + ds;
                unsigned int u1 = pb >> 16;     u1 = (u1 == 0xffffu) ? BIGU : u1 + ds;
                b0 = min(b0, min(v0, u0));
                b1 = min(b1, min(v1, u1));
            }
            dfa[i] = (float)((h0 == 0xffffu) ? b0 : h0);
            dfb[i] = (float)((h1 == 0xffffu) ? b1 : h1);
        } else {
            dfa[i] = (float)h0;
            dfb[i] = (float)h1;
        }
    }

    // polarity exchange through pol1's own (now dead) sg region, then combine:
    // field^2 = a + b + 2*sqrt(a*b)
    if (pol) {
        float* fdst = (float*)&sg[w][0];          // own region: no other reader
#pragma unroll
        for (int i = 0; i < 8; i++) {
            int j = i * 32 + lane;
            fdst[j] = dfa[i];
            fdst[256 + j] = dfb[i];
        }
    }
    __syncthreads();
    if (!pol) {
        const float* fsrc = (const float*)&sg[w + 1][0];
        float* o0 = g_f2 + (size_t)m * HW + (size_t)r0g * Ww;
        float* o1 = o0 + Ww;
#pragma unroll
        for (int i = 0; i < 8; i++) {
            int j = i * 32 + lane;
            float a = dfa[i], b = fsrc[j];
            o0[j] = a + b + 2.0f * __fsqrt_rn(a * b);
            float a2 = dfb[i], b2v = fsrc[256 + j];
            o1[j] = a2 + b2v + 2.0f * __fsqrt_rn(a2 * b2v);
        }
    }
}

// ---------------- K4: loss reduction + last-block finalize (R8 form) ---------
__global__ void k4_loss(const float* __restrict__ pred, const void* __restrict__ tgt,
                        float* __restrict__ outp) {
    int pix = blockIdx.x * 256 + threadIdx.x;
    int b = pix >> 16;
    int hw = pix & (HW - 1);
    const float* p = pred + (size_t)b * Cz * HW + hw;

    int t = load_target(tgt, pix);

    float v[Cz];
    float mx = -1e30f;
#pragma unroll
    for (int c = 0; c < Cz; c++) {
        v[c] = p[c * HW];
        mx = fmaxf(mx, v[c]);
    }
    float s = 0.0f;
#pragma unroll
    for (int c = 0; c < Cz; c++) {
        v[c] = expf(v[c] - mx);
        s += v[c];
    }
    float inv = 1.0f / s;

    double acc = 0.0;
#pragma unroll
    for (int c = 0; c < Cz; c++) {
        float fP2 = g_f2[(size_t)(b * Cz + c) * HW + hw];
        float fT2 = g_f2[(size_t)(HALFM + b * Cz + c) * HW + hw];
        float e = v[c] * inv - ((c == t) ? 1.0f : 0.0f);
        acc += (double)(e * e * (fP2 + fT2));
    }

    __shared__ double sred[256];
    sred[threadIdx.x] = acc;
    __syncthreads();
    for (int st = 128; st > 0; st >>= 1) {
        if (threadIdx.x < st) sred[threadIdx.x] += sred[threadIdx.x + st];
        __syncthreads();
    }
    if (threadIdx.x == 0) {
        atomicAdd(&g_acc[0], sred[0]);
        __threadfence();
        unsigned int prev = atomicAdd(&g_done, 1u);
        if (prev == (unsigned int)(gridDim.x - 1)) {
            __threadfence();
            volatile double* va = g_acc;
            double S = va[0];
            double CE = va[1];
            double N = (double)Bz * (double)HW;
            outp[0] = (float)(S / N / (double)Cz / (double)Bz / 3.0 - CE / N);
        }
    }
}

// ---------------- launch -----------------------------------------------------
extern "C" void kernel_launch(void* const* d_in, const int* in_sizes, int n_in,
                              void* d_out, int out_size) {
    const float* pred = (const float*)d_in[0];
    const void*  tgt  = d_in[1];
    float* out = (float*)d_out;

    k0_init<<<1, 128>>>((const unsigned int*)tgt);
    k1_masks<<<(Bz * HW) / 256, 256>>>(pred, tgt);
    k2_cols<<<dim3(NMASK, 4), 256>>>();
    k3_win<<<dim3(NMASK, Hh / 8), 256>>>();
    k4_loss<<<(Bz * HW) / 256, 256>>>(pred, tgt, out);
    (void)in_sizes; (void)n_in; (void)out_size;
}

// round 13
// speedup vs baseline: 1.4612x; 1.1418x over previous
#include <cuda_runtime.h>
#include <math.h>

#define Bz 4
#define Cz 12
#define Hh 256
#define Ww 256
#define HW 65536
#define NMASK 96
#define HALFM 48
#define SENT16 65535u
#define SENT_F 1e12f        // == fl32(1e6f*1e6f)
#define SCAN_INF (1 << 20)
#define CFAKE 10000
#define BIGU 0x0FFFFFFFu

// ---------------- scratch ----------------------------------------------------
__device__ unsigned char g_mask[NMASK * HW];
__device__ unsigned int  g_g[NMASK * HW];        // packed col dist (lo=fg, hi=bg)
__device__ float         g_f2[NMASK * HW];       // field^2 per mask
__device__ int           g_hasfg[NMASK];
__device__ int           g_anyfalse[NMASK];
__device__ double        g_acc[2];               // [0]=hausdorff S, [1]=sum logp
__device__ int           g_is64;
__device__ unsigned int  g_done;

// ---------------- K0 ---------------------------------------------------------
__global__ void k0_init(const unsigned int* __restrict__ tgt_words) {
    int t = threadIdx.x;                          // 128 threads
    __shared__ int s_nz;
    if (t == 0) s_nz = 0;
    __syncthreads();
    if (tgt_words[2 * t + 1] != 0u) atomicOr(&s_nz, 1);
    if (t < NMASK) { g_hasfg[t] = 0; g_anyfalse[t] = 0; }
    __syncthreads();
    if (t == 0) {
        g_is64 = (s_nz == 0);
        g_acc[0] = 0.0;
        g_acc[1] = 0.0;
        g_done = 0u;
    }
}

__device__ __forceinline__ int load_target(const void* t, int idx) {
    if (g_is64) return (int)((const long long*)t)[idx];
    return ((const int*)t)[idx];
}

// ---------------- K1: softmax -> masks, CE partial ---------------------------
__global__ void k1_masks(const float* __restrict__ pred, const void* __restrict__ tgt) {
    int pix = blockIdx.x * 256 + threadIdx.x;
    int b = pix >> 16;
    int hw = pix & (HW - 1);
    const float* p = pred + (size_t)b * Cz * HW + hw;

    int t = load_target(tgt, pix);

    float v[Cz];
    float mx = -1e30f;
    float xt = 0.0f;
#pragma unroll
    for (int c = 0; c < Cz; c++) {
        v[c] = p[c * HW];
        mx = fmaxf(mx, v[c]);
        if (c == t) xt = v[c];
    }
    float s = 0.0f;
#pragma unroll
    for (int c = 0; c < Cz; c++) {
        v[c] = expf(v[c] - mx);
        s += v[c];
    }
    float inv = 1.0f / s;
#pragma unroll
    for (int c = 0; c < Cz; c++) {
        g_mask[(size_t)(b * Cz + c) * HW + hw] = (unsigned char)(v[c] * inv > 0.5f);
        g_mask[(size_t)(HALFM + b * Cz + c) * HW + hw] = (unsigned char)(c == t);
    }

    float logp = xt - mx - logf(s);

    __shared__ float sred[256];
    sred[threadIdx.x] = logp;
    __syncthreads();
    for (int st = 128; st > 0; st >>= 1) {
        if (threadIdx.x < st) sred[threadIdx.x] += sred[threadIdx.x + st];
        __syncthreads();
    }
    if (threadIdx.x == 0) atomicAdd(&g_acc[1], (double)sred[0]);
}

// ---------------- K2: segmented column EDT (exact) ---------------------------
__global__ void __launch_bounds__(256) k2_cols() {
    __shared__ unsigned short sfwd[Hh][64];
    __shared__ unsigned short ssum[2][4][64];

    int tid = threadIdx.x;
    int col = tid & 63;
    int seg = tid >> 6;
    int m = blockIdx.x;
    int w = blockIdx.y * 64 + col;
    const unsigned char* msk = g_mask + (size_t)m * HW + w;

    int c1 = 255, c2 = 255;
    int ff1 = 255, ff2 = 255;
    int any = 0, anyf = 0;
#pragma unroll 8
    for (int i = 0; i < 64; i++) {
        int mv = msk[(seg * 64 + i) * Ww];
        any |= mv;
        anyf |= (mv ^ 1);
        c1 = mv ? min(c1 + 1, 255) : 0;
        c2 = mv ? 0 : min(c2 + 1, 255);
        if (!mv && ff1 == 255) ff1 = i;
        if (mv && ff2 == 255) ff2 = i;
        sfwd[seg * 64 + i][col] = (unsigned short)(c1 | (c2 << 8));
    }
    ssum[0][seg][col] = (unsigned short)(c1 | (c2 << 8));
    ssum[1][seg][col] = (unsigned short)(ff1 | (ff2 << 8));

    int anyb = __syncthreads_or(any);
    if (tid == 0 && anyb) atomicOr(&g_hasfg[m], 1);
    int anyfb = __syncthreads_or(anyf);
    if (tid == 0 && anyfb) atomicOr(&g_anyfalse[m], 1);

    int af1 = 0, af2 = 0;
#pragma unroll
    for (int s = 0; s < 4; s++) {
        unsigned int fp = ssum[1][s][col];
        af1 |= ((fp & 255u) != 255u);
        af2 |= (((fp >> 8) & 255u) != 255u);
    }
    int cin1 = CFAKE, cin2 = CFAKE;
    for (int s = 0; s < seg; s++) {
        unsigned int sp = ssum[0][s][col];
        int s1 = sp & 255, s2 = (sp >> 8) & 255;
        cin1 = min((s1 == 255) ? CFAKE : s1, cin1 + 64);
        cin2 = min((s2 == 255) ? CFAKE : s2, cin2 + 64);
    }
    int bin1 = CFAKE, bin2 = CFAKE;
    for (int s = 3; s > seg; s--) {
        unsigned int fp = ssum[1][s][col];
        int f1 = fp & 255, f2 = (fp >> 8) & 255;
        bin1 = min((f1 == 255) ? CFAKE : f1, bin1 + 64);
        bin2 = min((f2 == 255) ? CFAKE : f2, bin2 + 64);
    }

    unsigned int* gout = g_g + (size_t)m * HW + w;
    int b1 = bin1, b2 = bin2;
#pragma unroll 8
    for (int i = 63; i >= 0; i--) {
        unsigned int fw = sfwd[seg * 64 + i][col];
        int f1 = fw & 255, f2 = (fw >> 8) & 255;
        b1 = (f1 == 0) ? 0 : b1 + 1;
        b2 = (f2 == 0) ? 0 : b2 + 1;
        int fa1 = min(f1, cin1 + i + 1);
        int fa2 = min(f2, cin2 + i + 1);
        int g1 = min(fa1, b1);
        int g2v = min(fa2, b2);
        unsigned int o1 = af1 ? (unsigned int)g1 : SENT16;
        unsigned int o2 = af2 ? (unsigned int)g2v : SENT16;
        gout[(seg * 64 + i) * Ww] = o1 | (o2 << 16);
    }
}

// ---------------- K3: 4-row u16-packed window scan, select-write field^2 -----
// field^2 = d_opp^2: at each pixel exactly one polarity's d^2 is nonzero, so
// the warp that computed the nonzero value writes it; no sqrt, no exchange.
// Block: 8 warps = 2 polarities x 4 row-groups of 4 rows; block covers 16 rows.
// Chunk radii R are computed in registers + shuffles (no smem transpose):
// smem = sg only = 48KB exactly.
__global__ void __launch_bounds__(256) k3_win() {
    __shared__ uint2 sg[8][768];                  // 48KB: per warp [pad|data|pad]

    int tid = threadIdx.x;
    int w = tid >> 5;
    int lane = tid & 31;
    int pol = w >> 2;                             // 0 = fg(lo half), 1 = bg(hi half)
    int rg = w & 3;
    int m = blockIdx.x;

    int hfg = g_hasfg[m];
    int afl = g_anyfalse[m];
    if (!hfg || !afl) {                           // empty mask -> 0; all-true -> 1e12
        float val = hfg ? SENT_F : 0.0f;
        float* o = g_f2 + (size_t)m * HW + (size_t)blockIdx.y * 16 * Ww;
        for (int i = tid; i < 16 * Ww; i += 256) o[i] = val;
        return;
    }

    int r0 = blockIdx.y * 16 + rg * 4;
    const unsigned int* g0 = g_g + (size_t)m * HW + (size_t)r0 * Ww;

    // pads = saturated-inf
    for (int i = lane; i < 256; i += 32) {
        sg[w][i] = make_uint2(0xFFFFFFFFu, 0xFFFFFFFFu);
        sg[w][512 + i] = make_uint2(0xFFFFFFFFu, 0xFFFFFFFFu);
    }

    int x[8];
    int base = lane * 8;
    unsigned int p01[8], p23[8];
#pragma unroll
    for (int r = 0; r < 4; r++) {
        const uint4* ar = (const uint4*)(g0 + r * Ww);
        uint4 qa = ar[lane * 2], qb = ar[lane * 2 + 1];
        unsigned int rw[8] = {qa.x, qa.y, qa.z, qa.w, qb.x, qb.y, qb.z, qb.w};
#pragma unroll
        for (int i = 0; i < 8; i++) {
            unsigned int g = pol ? (rw[i] >> 16) : (rw[i] & 0xffffu);
            unsigned int q = (g == 0xffffu) ? 0xffffu : g * g;   // u16 exact
            if (r == 0) p01[i] = q;
            else if (r == 1) { p01[i] |= q << 16; x[i] = (int)min(g, 300u); }
            else if (r == 2) p23[i] = q;
            else p23[i] |= q << 16;
        }
    }
#pragma unroll
    for (int i = 0; i < 8; i++) sg[w][256 + base + i] = make_uint2(p01[i], p23[i]);

    // chamfer bound on row 1; rows {0,2,3} covered by ub+2 (1-Lipschitz in h)
    int f[8];
    int run = SCAN_INF;
#pragma unroll
    for (int i = 0; i < 8; i++) { run = min(x[i], run + 1); f[i] = run; }
    int v = run;
#pragma unroll
    for (int s = 1; s < 32; s <<= 1) {
        int o = __shfl_up_sync(0xffffffffu, v, s);
        if (lane >= s) v = min(v, o + 8 * s);
    }
    int e = __shfl_up_sync(0xffffffffu, v, 1);
    if (lane == 0) e = SCAN_INF;
#pragma unroll
    for (int i = 0; i < 8; i++) f[i] = min(f[i], e + 1 + i);

    int bw[8];
    run = SCAN_INF;
#pragma unroll
    for (int i = 7; i >= 0; i--) { run = min(x[i], run + 1); bw[i] = run; }
    int vb = run;
#pragma unroll
    for (int s = 1; s < 32; s <<= 1) {
        int o = __shfl_down_sync(0xffffffffu, vb, s);
        if (lane + s < 32) vb = min(vb, o + 8 * s);
    }
    int eb = __shfl_down_sync(0xffffffffu, vb, 1);
    if (lane == 31) eb = SCAN_INF;

    // per-lane max ub over its 8 j's, then group-of-4 max -> chunk radii
    int mloc = 0;
#pragma unroll
    for (int i = 0; i < 8; i++) {
        int ub = min(min(f[i], bw[i]), min(eb + 8 - i, 255));
        mloc = max(mloc, min(ub + 2, 255));
    }
    int m4 = mloc;
    m4 = max(m4, __shfl_xor_sync(0xffffffffu, m4, 1));
    m4 = max(m4, __shfl_xor_sync(0xffffffffu, m4, 2));
    // lane 4i (and its group) now holds chunk i's radius

    // main packed loop: 8 chunks x 32 cols, 4 rows per lane per chunk
    const uint2* gp = &sg[w][256];
#pragma unroll
    for (int i = 0; i < 8; i++) {
        int j = i * 32 + lane;
        unsigned int R = (unsigned int)__shfl_sync(0xffffffffu, m4, i * 4);
        uint2 self = gp[j];
        unsigned int best01 = self.x, best23 = self.y;
        unsigned int dd2 = 0u, inc2 = 0x00010001u;
        int nb = ((int)R + 7) >> 3;
        int dbase = 0;
        for (int bl = 0; bl < nb; bl++) {
#pragma unroll
            for (int u = 1; u <= 8; u++) {
                int d = dbase + u;                // d <= 256; indices in [0,767]
                dd2 += inc2; inc2 += 0x00020002u;
                uint2 ca = gp[j + d];
                uint2 cb = gp[j - d];
                best01 = __vminu2(best01, __vaddus2(__vminu2(ca.x, cb.x), dd2));
                best23 = __vminu2(best23, __vaddus2(__vminu2(ca.y, cb.y), dd2));
            }
            dbase += 8;
            unsigned int hm = max(max(best01 & 0xffffu, best01 >> 16),
                                  max(best23 & 0xffffu, best23 >> 16));
            hm = __reduce_max_sync(0xffffffffu, hm);
            if ((unsigned int)((dbase + 1) * (dbase + 1)) >= hm) break;
        }

        unsigned int h[4] = {best01 & 0xffffu, best01 >> 16,
                             best23 & 0xffffu, best23 >> 16};
        int ov = (h[0] == 0xffffu) | (h[1] == 0xffffu) |
                 (h[2] == 0xffffu) | (h[3] == 0xffffu);
        if (__ballot_sync(0xffffffffu, ov)) {
            // exact u32 fallback (rare: true d^2 > 65535 -> R was 255)
            unsigned int b4[4] = {BIGU, BIGU, BIGU, BIGU};
            for (int d = 0; d <= 255; d++) {
                unsigned int ds = (unsigned int)(d * d);
                uint2 pa = gp[j + d], pb = gp[j - d];
                unsigned int cs[4] = {
                    min(pa.x & 0xffffu, pb.x & 0xffffu),
                    min(pa.x >> 16,     pb.x >> 16),
                    min(pa.y & 0xffffu, pb.y & 0xffffu),
                    min(pa.y >> 16,     pb.y >> 16)};
#pragma unroll
                for (int r = 0; r < 4; r++) {
                    unsigned int c = (cs[r] == 0xffffu) ? BIGU : cs[r] + ds;
                    b4[r] = min(b4[r], c);
                }
            }
#pragma unroll
            for (int r = 0; r < 4; r++) if (h[r] == 0xffffu) h[r] = b4[r];
        }

        // select-write: nonzero d^2 means this pixel's field^2 belongs to us
        float* orow = g_f2 + (size_t)m * HW + (size_t)r0 * Ww + j;
#pragma unroll
        for (int r = 0; r < 4; r++) {
            if (h[r] > 0u) orow[r * Ww] = (float)h[r];
        }
    }
}

// ---------------- K4: loss reduction + last-block finalize -------------------
__global__ void k4_loss(const float* __restrict__ pred, const void* __restrict__ tgt,
                        float* __restrict__ outp) {
    int pix = blockIdx.x * 256 + threadIdx.x;
    int b = pix >> 16;
    int hw = pix & (HW - 1);
    const float* p = pred + (size_t)b * Cz * HW + hw;

    int t = load_target(tgt, pix);

    float v[Cz];
    float mx = -1e30f;
#pragma unroll
    for (int c = 0; c < Cz; c++) {
        v[c] = p[c * HW];
        mx = fmaxf(mx, v[c]);
    }
    float s = 0.0f;
#pragma unroll
    for (int c = 0; c < Cz; c++) {
        v[c] = expf(v[c] - mx);
        s += v[c];
    }
    float inv = 1.0f / s;

    double acc = 0.0;
#pragma unroll
    for (int c = 0; c < Cz; c++) {
        float fP2 = g_f2[(size_t)(b * Cz + c) * HW + hw];
        float fT2 = g_f2[(size_t)(HALFM + b * Cz + c) * HW + hw];
        float e = v[c] * inv - ((c == t) ? 1.0f : 0.0f);
        acc += (double)(e * e * (fP2 + fT2));
    }

    __shared__ double sred[256];
    sred[threadIdx.x] = acc;
    __syncthreads();
    for (int st = 128; st > 0; st >>= 1) {
        if (threadIdx.x < st) sred[threadIdx.x] += sred[threadIdx.x + st];
        __syncthreads();
    }
    if (threadIdx.x == 0) {
        atomicAdd(&g_acc[0], sred[0]);
        __threadfence();
        unsigned int prev = atomicAdd(&g_done, 1u);
        if (prev == (unsigned int)(gridDim.x - 1)) {
            __threadfence();
            volatile double* va = g_acc;
            double S = va[0];
            double CE = va[1];
            double N = (double)Bz * (double)HW;
            outp[0] = (float)(S / N / (double)Cz / (double)Bz / 3.0 - CE / N);
        }
    }
}

// ---------------- launch -----------------------------------------------------
extern "C" void kernel_launch(void* const* d_in, const int* in_sizes, int n_in,
                              void* d_out, int out_size) {
    const float* pred = (const float*)d_in[0];
    const void*  tgt  = d_in[1];
    float* out = (float*)d_out;

    k0_init<<<1, 128>>>((const unsigned int*)tgt);
    k1_masks<<<(Bz * HW) / 256, 256>>>(pred, tgt);
    k2_cols<<<dim3(NMASK, 4), 256>>>();
    k3_win<<<dim3(NMASK, Hh / 16), 256>>>();
    k4_loss<<<(Bz * HW) / 256, 256>>>(pred, tgt, out);
    (void)in_sizes; (void)n_in; (void)out_size;
}

// round 15
// speedup vs baseline: 1.5055x; 1.0303x over previous
#include <cuda_runtime.h>
#include <math.h>

#define Bz 4
#define Cz 12
#define Hh 256
#define Ww 256
#define HW 65536
#define NMASK 96
#define HALFM 48
#define SENT16 65535u
#define SCAN_INF (1 << 20)
#define CFAKE 10000
#define BIGU 0x0FFFFFFFu
#define K3_BLOCKS (NMASK * (Hh / 16))

// ---------------- scratch ----------------------------------------------------
__device__ unsigned char g_mask[NMASK * HW];
__device__ unsigned int  g_g[NMASK * HW];        // packed col dist (lo=fg, hi=bg)
__device__ float         g_e2[HALFM * HW];       // (softmax - onehot)^2 planes
__device__ int           g_hasfg[NMASK];
__device__ int           g_anyfalse[NMASK];
__device__ double        g_acc[2];               // [0]=hausdorff S, [1]=sum logp
__device__ int           g_is64;
__device__ unsigned int  g_done;

// ---------------- K0 ---------------------------------------------------------
__global__ void k0_init(const unsigned int* __restrict__ tgt_words) {
    int t = threadIdx.x;                          // 128 threads
    __shared__ int s_nz;
    if (t == 0) s_nz = 0;
    __syncthreads();
    if (tgt_words[2 * t + 1] != 0u) atomicOr(&s_nz, 1);
    if (t < NMASK) { g_hasfg[t] = 0; g_anyfalse[t] = 0; }
    __syncthreads();
    if (t == 0) {
        g_is64 = (s_nz == 0);
        g_acc[0] = 0.0;
        g_acc[1] = 0.0;
        g_done = 0u;
    }
}

__device__ __forceinline__ int load_target(const void* t, int idx) {
    if (g_is64) return (int)((const long long*)t)[idx];
    return ((const int*)t)[idx];
}

// ---------------- K1: softmax -> masks + e2 planes + CE partial --------------
__global__ void k1_masks(const float* __restrict__ pred, const void* __restrict__ tgt) {
    int pix = blockIdx.x * 256 + threadIdx.x;
    int b = pix >> 16;
    int hw = pix & (HW - 1);
    const float* p = pred + (size_t)b * Cz * HW + hw;

    int t = load_target(tgt, pix);

    float v[Cz];
    float mx = -1e30f;
    float xt = 0.0f;
#pragma unroll
    for (int c = 0; c < Cz; c++) {
        v[c] = p[c * HW];
        mx = fmaxf(mx, v[c]);
        if (c == t) xt = v[c];
    }
    float s = 0.0f;
#pragma unroll
    for (int c = 0; c < Cz; c++) {
        v[c] = expf(v[c] - mx);
        s += v[c];
    }
    float inv = 1.0f / s;
#pragma unroll
    for (int c = 0; c < Cz; c++) {
        float pv = v[c] * inv;
        g_mask[(size_t)(b * Cz + c) * HW + hw] = (unsigned char)(pv > 0.5f);
        g_mask[(size_t)(HALFM + b * Cz + c) * HW + hw] = (unsigned char)(c == t);
        float e = pv - ((c == t) ? 1.0f : 0.0f);
        g_e2[(size_t)(b * Cz + c) * HW + hw] = e * e;
    }

    float logp = xt - mx - logf(s);

    __shared__ float sred[256];
    sred[threadIdx.x] = logp;
    __syncthreads();
    for (int st = 128; st > 0; st >>= 1) {
        if (threadIdx.x < st) sred[threadIdx.x] += sred[threadIdx.x + st];
        __syncthreads();
    }
    if (threadIdx.x == 0) atomicAdd(&g_acc[1], (double)sred[0]);
}

// ---------------- K2: segmented column EDT (exact) ---------------------------
__global__ void __launch_bounds__(256) k2_cols() {
    __shared__ unsigned short sfwd[Hh][64];
    __shared__ unsigned short ssum[2][4][64];

    int tid = threadIdx.x;
    int col = tid & 63;
    int seg = tid >> 6;
    int m = blockIdx.x;
    int w = blockIdx.y * 64 + col;
    const unsigned char* msk = g_mask + (size_t)m * HW + w;

    int c1 = 255, c2 = 255;
    int ff1 = 255, ff2 = 255;
    int any = 0, anyf = 0;
#pragma unroll 8
    for (int i = 0; i < 64; i++) {
        int mv = msk[(seg * 64 + i) * Ww];
        any |= mv;
        anyf |= (mv ^ 1);
        c1 = mv ? min(c1 + 1, 255) : 0;
        c2 = mv ? 0 : min(c2 + 1, 255);
        if (!mv && ff1 == 255) ff1 = i;
        if (mv && ff2 == 255) ff2 = i;
        sfwd[seg * 64 + i][col] = (unsigned short)(c1 | (c2 << 8));
    }
    ssum[0][seg][col] = (unsigned short)(c1 | (c2 << 8));
    ssum[1][seg][col] = (unsigned short)(ff1 | (ff2 << 8));

    int anyb = __syncthreads_or(any);
    if (tid == 0 && anyb) atomicOr(&g_hasfg[m], 1);
    int anyfb = __syncthreads_or(anyf);
    if (tid == 0 && anyfb) atomicOr(&g_anyfalse[m], 1);

    int af1 = 0, af2 = 0;
#pragma unroll
    for (int s = 0; s < 4; s++) {
        unsigned int fp = ssum[1][s][col];
        af1 |= ((fp & 255u) != 255u);
        af2 |= (((fp >> 8) & 255u) != 255u);
    }
    int cin1 = CFAKE, cin2 = CFAKE;
    for (int s = 0; s < seg; s++) {
        unsigned int sp = ssum[0][s][col];
        int s1 = sp & 255, s2 = (sp >> 8) & 255;
        cin1 = min((s1 == 255) ? CFAKE : s1, cin1 + 64);
        cin2 = min((s2 == 255) ? CFAKE : s2, cin2 + 64);
    }
    int bin1 = CFAKE, bin2 = CFAKE;
    for (int s = 3; s > seg; s--) {
        unsigned int fp = ssum[1][s][col];
        int f1 = fp & 255, f2 = (fp >> 8) & 255;
        bin1 = min((f1 == 255) ? CFAKE : f1, bin1 + 64);
        bin2 = min((f2 == 255) ? CFAKE : f2, bin2 + 64);
    }

    unsigned int* gout = g_g + (size_t)m * HW + w;
    int b1 = bin1, b2 = bin2;
#pragma unroll 8
    for (int i = 63; i >= 0; i--) {
        unsigned int fw = sfwd[seg * 64 + i][col];
        int f1 = fw & 255, f2 = (fw >> 8) & 255;
        b1 = (f1 == 0) ? 0 : b1 + 1;
        b2 = (f2 == 0) ? 0 : b2 + 1;
        int fa1 = min(f1, cin1 + i + 1);
        int fa2 = min(f2, cin2 + i + 1);
        int g1 = min(fa1, b1);
        int g2v = min(fa2, b2);
        unsigned int o1 = af1 ? (unsigned int)g1 : SENT16;
        unsigned int o2 = af2 ? (unsigned int)g2v : SENT16;
        gout[(seg * 64 + i) * Ww] = o1 | (o2 << 16);
    }
}

// ---------------- K3: 4-row window scan + fused loss accumulate --------------
// field^2 = d_opp^2 (exactly one polarity nonzero per pixel), so each warp
// accumulates acc += e2 * h over its own h (h=0 pixels belong to the other
// polarity warp and contribute 0). No f2 array, no k4. Pads shrunk to 128
// (fast path R<=128; rare R>128 or u16 saturation -> bounds-checked u32 scan).
// Last block finalizes the scalar output.
__global__ void __launch_bounds__(256, 6) k3_win(float* __restrict__ outp) {
    __shared__ uint2 sg[8][512];                  // 32KB: [128 pad|256 data|128 pad]
    __shared__ double swarp[8];

    int tid = threadIdx.x;
    int w = tid >> 5;
    int lane = tid & 31;
    int pol = w >> 2;                             // 0 = fg(lo half), 1 = bg(hi half)
    int rg = w & 3;
    int m = blockIdx.x;
    int pm = (m < HALFM) ? m : m - HALFM;

    int hfg = g_hasfg[m];
    int afl = g_anyfalse[m];

    double accd = 0.0;

    if (hfg && !afl) {
        // full-true mask: field^2 == 1e12 everywhere -> 1e12 * sum(e2)
        const float* e = g_e2 + (size_t)pm * HW + (size_t)blockIdx.y * 16 * Ww;
        for (int i = tid; i < 16 * Ww; i += 256) accd += (double)e[i];
        accd *= 1e12;
    } else if (hfg) {
        // main path
        int r0 = blockIdx.y * 16 + rg * 4;
        const unsigned int* g0 = g_g + (size_t)m * HW + (size_t)r0 * Ww;

        // pads = saturated-inf
#pragma unroll
        for (int i = lane; i < 128; i += 32) {
            sg[w][i] = make_uint2(0xFFFFFFFFu, 0xFFFFFFFFu);
            sg[w][384 + i] = make_uint2(0xFFFFFFFFu, 0xFFFFFFFFu);
        }

        int x[8];
        int base = lane * 8;
        unsigned int p01[8], p23[8];
#pragma unroll
        for (int r = 0; r < 4; r++) {
            const uint4* ar = (const uint4*)(g0 + r * Ww);
            uint4 qa = ar[lane * 2], qb = ar[lane * 2 + 1];
            unsigned int rw[8] = {qa.x, qa.y, qa.z, qa.w, qb.x, qb.y, qb.z, qb.w};
#pragma unroll
            for (int i = 0; i < 8; i++) {
                unsigned int g = pol ? (rw[i] >> 16) : (rw[i] & 0xffffu);
                unsigned int q = (g == 0xffffu) ? 0xffffu : g * g;   // u16 exact
                if (r == 0) p01[i] = q;
                else if (r == 1) { p01[i] |= q << 16; x[i] = (int)min(g, 300u); }
                else if (r == 2) p23[i] = q;
                else p23[i] |= q << 16;
            }
        }
#pragma unroll
        for (int i = 0; i < 8; i++) sg[w][128 + base + i] = make_uint2(p01[i], p23[i]);

        // chamfer bound on row 1; rows {0,2,3} covered by ub+2 (1-Lipschitz in h)
        int f[8];
        int run = SCAN_INF;
#pragma unroll
        for (int i = 0; i < 8; i++) { run = min(x[i], run + 1); f[i] = run; }
        int v = run;
#pragma unroll
        for (int s = 1; s < 32; s <<= 1) {
            int o = __shfl_up_sync(0xffffffffu, v, s);
            if (lane >= s) v = min(v, o + 8 * s);
        }
        int e = __shfl_up_sync(0xffffffffu, v, 1);
        if (lane == 0) e = SCAN_INF;
#pragma unroll
        for (int i = 0; i < 8; i++) f[i] = min(f[i], e + 1 + i);

        int bw[8];
        run = SCAN_INF;
#pragma unroll
        for (int i = 7; i >= 0; i--) { run = min(x[i], run + 1); bw[i] = run; }
        int vb = run;
#pragma unroll
        for (int s = 1; s < 32; s <<= 1) {
            int o = __shfl_down_sync(0xffffffffu, vb, s);
            if (lane + s < 32) vb = min(vb, o + 8 * s);
        }
        int eb = __shfl_down_sync(0xffffffffu, vb, 1);
        if (lane == 31) eb = SCAN_INF;

        int mloc = 0;
#pragma unroll
        for (int i = 0; i < 8; i++) {
            int ub = min(min(f[i], bw[i]), min(eb + 8 - i, 255));
            mloc = max(mloc, min(ub + 2, 255));
        }
        int m4 = mloc;
        m4 = max(m4, __shfl_xor_sync(0xffffffffu, m4, 1));
        m4 = max(m4, __shfl_xor_sync(0xffffffffu, m4, 2));

        const uint2* gp = &sg[w][128];
        const float* e2base = g_e2 + (size_t)pm * HW + (size_t)r0 * Ww;
        float accf = 0.0f;
#pragma unroll
        for (int i = 0; i < 8; i++) {
            int j = i * 32 + lane;
            unsigned int R = (unsigned int)__shfl_sync(0xffffffffu, m4, i * 4);

            // prefetch e2 for this chunk (L2-resident; hidden by window loop)
            const float* e0 = e2base + j;
            float ev0 = e0[0];
            float ev1 = e0[Ww];
            float ev2 = e0[2 * Ww];
            float ev3 = e0[3 * Ww];

            unsigned int h[4];
            bool need_fb = (R > 128u);            // warp-uniform
            if (!need_fb) {
                uint2 self = gp[j];
                unsigned int best01 = self.x, best23 = self.y;
                unsigned int dd2 = 0u, inc2 = 0x00010001u;
                int nb = ((int)R + 7) >> 3;
                int dbase = 0;
                for (int bl = 0; bl < nb; bl++) {
#pragma unroll
                    for (int u = 1; u <= 8; u++) {
                        int d = dbase + u;        // d <= 128; indices in [0,511]
                        dd2 += inc2; inc2 += 0x00020002u;
                        uint2 ca = gp[j + d];
                        uint2 cb = gp[j - d];
                        best01 = __vminu2(best01, __vaddus2(__vminu2(ca.x, cb.x), dd2));
                        best23 = __vminu2(best23, __vaddus2(__vminu2(ca.y, cb.y), dd2));
                    }
                    dbase += 8;
                    unsigned int hm = max(max(best01 & 0xffffu, best01 >> 16),
                                          max(best23 & 0xffffu, best23 >> 16));
                    hm = __reduce_max_sync(0xffffffffu, hm);
                    if ((unsigned int)((dbase + 1) * (dbase + 1)) >= hm) break;
                }
                h[0] = best01 & 0xffffu; h[1] = best01 >> 16;
                h[2] = best23 & 0xffffu; h[3] = best23 >> 16;
                int ov = (h[0] == 0xffffu) | (h[1] == 0xffffu) |
                         (h[2] == 0xffffu) | (h[3] == 0xffffu);
                need_fb = (__ballot_sync(0xffffffffu, ov) != 0u);
            } else {
#pragma unroll
                for (int r = 0; r < 4; r++) h[r] = 0xffffu;
            }

            if (need_fb) {
                // exact u32 full scan, bounds-checked (no pads needed)
                unsigned int b4[4] = {BIGU, BIGU, BIGU, BIGU};
                for (int d = 0; d <= 255; d++) {
                    unsigned int ds = (unsigned int)(d * d);
                    if (j + d < 256) {
                        uint2 pa = gp[j + d];
                        unsigned int c0 = pa.x & 0xffffu, c1v = pa.x >> 16;
                        unsigned int c2v = pa.y & 0xffffu, c3 = pa.y >> 16;
                        if (c0 != 0xffffu) b4[0] = min(b4[0], c0 + ds);
                        if (c1v != 0xffffu) b4[1] = min(b4[1], c1v + ds);
                        if (c2v != 0xffffu) b4[2] = min(b4[2], c2v + ds);
                        if (c3 != 0xffffu) b4[3] = min(b4[3], c3 + ds);
                    }
                    if (j - d >= 0 && d > 0) {
                        uint2 pb = gp[j - d];
                        unsigned int c0 = pb.x & 0xffffu, c1v = pb.x >> 16;
                        unsigned int c2v = pb.y & 0xffffu, c3 = pb.y >> 16;
                        if (c0 != 0xffffu) b4[0] = min(b4[0], c0 + ds);
                        if (c1v != 0xffffu) b4[1] = min(b4[1], c1v + ds);
                        if (c2v != 0xffffu) b4[2] = min(b4[2], c2v + ds);
                        if (c3 != 0xffffu) b4[3] = min(b4[3], c3 + ds);
                    }
                }
#pragma unroll
                for (int r = 0; r < 4; r++) if (h[r] == 0xffffu) h[r] = b4[r];
            }

            // fused accumulate: pixels owned by other polarity have h==0
            accf = fmaf(ev0, (float)h[0], accf);
            accf = fmaf(ev1, (float)h[1], accf);
            accf = fmaf(ev2, (float)h[2], accf);
            accf = fmaf(ev3, (float)h[3], accf);
        }
        accd = (double)accf;
    }
    // (empty mask: accd stays 0)

    // block reduction + global accumulate + last-block finalize
#pragma unroll
    for (int s = 16; s > 0; s >>= 1)
        accd += __shfl_down_sync(0xffffffffu, accd, s);
    if (lane == 0) swarp[w] = accd;
    __syncthreads();
    if (tid == 0) {
        double tot = 0.0;
#pragma unroll
        for (int i = 0; i < 8; i++) tot += swarp[i];
        atomicAdd(&g_acc[0], tot);
        __threadfence();
        unsigned int prev = atomicAdd(&g_done, 1u);
        if (prev == (unsigned int)(K3_BLOCKS - 1)) {
            __threadfence();
            volatile double* va = g_acc;
            double S = va[0];
            double CE = va[1];
            double N = (double)Bz * (double)HW;
            outp[0] = (float)(S / N / (double)Cz / (double)Bz / 3.0 - CE / N);
        }
    }
}

// ---------------- launch -----------------------------------------------------
extern "C" void kernel_launch(void* const* d_in, const int* in_sizes, int n_in,
                              void* d_out, int out_size) {
    const float* pred = (const float*)d_in[0];
    const void*  tgt  = d_in[1];
    float* out = (float*)d_out;

    k0_init<<<1, 128>>>((const unsigned int*)tgt);
    k1_masks<<<(Bz * HW) / 256, 256>>>(pred, tgt);
    k2_cols<<<dim3(NMASK, 4), 256>>>();
    k3_win<<<dim3(NMASK, Hh / 16), 256>>>(out);
    (void)in_sizes; (void)n_in; (void)out_size;
}